// round 15
// baseline (speedup 1.0000x reference)
#include <cuda_runtime.h>
#include <math.h>
#include <stdint.h>

// Shapes (fixed for this problem)
#define BB  1024   // batch
#define PP  256    // patches
#define DD  1024   // dino dim
#define DC  512    // clip dim

#define NSPLIT 4   // split-K factor for both GEMMs

// Scratch (no allocation allowed)
__device__ float g_tn  [BB * DD];          // normalized t (fp32, argmax-critical)
__device__ float g_tnh [BB * DD];          // tf32-rounded tn (GEMM2 A)
__device__ float g_vbh [BB * DD];          // tf32-rounded vb  (GEMM2 B)
__device__ float g_th  [BB * DC];          // tf32 hi of text
__device__ float g_tl  [BB * DC];          // tf32 lo of text
__device__ float g_Wh  [DD * DC];          // tf32 hi of W
__device__ float g_Wl  [DD * DC];          // tf32 lo of W
__device__ float g_part[NSPLIT][BB * DD];  // split-K partial sums (reused)

__device__ __forceinline__ float f2tf32f(float f) {
    uint32_t u;
    asm("cvt.rna.tf32.f32 %0, %1;" : "=r"(u) : "f"(f));
    return __uint_as_float(u);
}
__device__ __forceinline__ uint32_t smem_u32(const void* p) {
    uint32_t r;
    asm("{ .reg .u64 t; cvta.to.shared.u64 t, %1; cvt.u32.u64 %0, t; }"
        : "=r"(r) : "l"(p));
    return r;
}

#define MMA_TF32(acc, a, b) \
    asm volatile( \
        "mma.sync.aligned.m16n8k8.row.col.f32.tf32.tf32.f32 " \
        "{%0,%1,%2,%3}, {%4,%5,%6,%7}, {%8,%9}, {%0,%1,%2,%3};" \
        : "+f"((acc)[0]), "+f"((acc)[1]), "+f"((acc)[2]), "+f"((acc)[3]) \
        : "r"((a)[0]), "r"((a)[1]), "r"((a)[2]), "r"((a)[3]), \
          "r"((b)[0]), "r"((b)[1]))

#define LDSM4(r0, r1, r2, r3, addr) \
    asm volatile("ldmatrix.sync.aligned.m8n8.x4.shared.b16 {%0,%1,%2,%3}, [%4];" \
        : "=r"(r0), "=r"(r1), "=r"(r2), "=r"(r3) : "r"(addr))

// ---------------------------------------------------------------------------
// Prep: hi/lo tf32 split of text and W (both 512K floats = 131072 float4).
// ---------------------------------------------------------------------------
__global__ void __launch_bounds__(256)
prep_split_kernel(const float* __restrict__ text, const float* __restrict__ W,
                  float* __restrict__ th, float* __restrict__ tl,
                  float* __restrict__ Wh, float* __restrict__ Wl)
{
    const int i = blockIdx.x * 256 + threadIdx.x;
    float4 a = ((const float4*)text)[i];
    float4 b = ((const float4*)W)[i];
    float4 ah = make_float4(f2tf32f(a.x), f2tf32f(a.y), f2tf32f(a.z), f2tf32f(a.w));
    float4 bh = make_float4(f2tf32f(b.x), f2tf32f(b.y), f2tf32f(b.z), f2tf32f(b.w));
    float4 al = make_float4(f2tf32f(a.x - ah.x), f2tf32f(a.y - ah.y),
                            f2tf32f(a.z - ah.z), f2tf32f(a.w - ah.w));
    float4 bl = make_float4(f2tf32f(b.x - bh.x), f2tf32f(b.y - bh.y),
                            f2tf32f(b.z - bh.z), f2tf32f(b.w - bh.w));
    ((float4*)th)[i] = ah; ((float4*)tl)[i] = al;
    ((float4*)Wh)[i] = bh; ((float4*)Wl)[i] = bl;
}

// ===========================================================================
// GEMM1 partial: split-tf32 (pre-split hi/lo inputs, no in-loop cvt),
// split-K over blockIdx.z. BM=BN=64, 128 threads, LDSM fragments.
// ===========================================================================
template<int K, int KS>
__global__ void __launch_bounds__(128)
gemm_split_part(const float* __restrict__ Ah, const float* __restrict__ Al,
                const float* __restrict__ Bh, const float* __restrict__ Bl,
                float* __restrict__ Cp)
{
    constexpr int PITCH = 68;            // hi at [0,32), lo at [32,64)
    constexpr int NKT   = KS / 32;

    __shared__ __align__(16) uint32_t As[64][PITCH];
    __shared__ __align__(16) uint32_t Bs[64][PITCH];

    const int tid  = threadIdx.x;
    const int lane = tid & 31;
    const int warp = tid >> 5;
    const int wm   = warp >> 1;
    const int wn   = warp & 1;

    const int m0 = blockIdx.y * 64;
    const int n0 = blockIdx.x * 64;
    const int kbase = blockIdx.z * KS;
    float* __restrict__ C = Cp + (size_t)blockIdx.z * (BB * DD);

    const int lr = tid >> 3;
    const int lc = tid & 7;

    const int q  = lane >> 3;
    const int jj = lane & 7;
    const int frow = jj + 8 * (q & 1);
    const int fcol = 4 * (q >> 1);

    const uint32_t aBase = smem_u32(&As[0][0]);
    const uint32_t bBase = smem_u32(&Bs[0][0]);
    const uint32_t aAddr = aBase + ((wm * 32 + frow) * PITCH + fcol) * 4;
    const uint32_t bAddr = bBase + ((wn * 32 + frow) * PITCH + fcol) * 4;
    constexpr uint32_t TILE16 = 16u * PITCH * 4;
    constexpr uint32_t LOOFF  = 32u * 4;

    float c[2][4][4];
    #pragma unroll
    for (int i = 0; i < 2; i++)
        #pragma unroll
        for (int j = 0; j < 4; j++)
            #pragma unroll
            for (int qq = 0; qq < 4; qq++) c[i][j][qq] = 0.f;

    uint4 pah[4], pal[4], pbh[4], pbl[4];

    auto load_tile = [&](int kk) {
        #pragma unroll
        for (int i = 0; i < 4; i++) {
            const int r = lr + i * 16;
            const size_t ao = (size_t)(m0 + r) * K + kk + lc * 4;
            const size_t bo = (size_t)(n0 + r) * K + kk + lc * 4;
            pah[i] = *(const uint4*)(Ah + ao);
            pal[i] = *(const uint4*)(Al + ao);
            pbh[i] = *(const uint4*)(Bh + bo);
            pbl[i] = *(const uint4*)(Bl + bo);
        }
    };
    auto store_tile = [&]() {
        #pragma unroll
        for (int i = 0; i < 4; i++) {
            const int r = lr + i * 16;
            *(uint4*)&As[r][lc * 4]      = pah[i];
            *(uint4*)&As[r][32 + lc * 4] = pal[i];
            *(uint4*)&Bs[r][lc * 4]      = pbh[i];
            *(uint4*)&Bs[r][32 + lc * 4] = pbl[i];
        }
    };

    load_tile(kbase);
    store_tile();
    __syncthreads();

    for (int kt = 0; kt < NKT; kt++) {
        if (kt + 1 < NKT) load_tile(kbase + (kt + 1) * 32);

        #pragma unroll
        for (int k8 = 0; k8 < 4; k8++) {
            const uint32_t ko = (uint32_t)k8 * 32;

            uint32_t af[2][4], afl[2][4];
            LDSM4(af[0][0],  af[0][1],  af[0][2],  af[0][3],  aAddr + ko);
            LDSM4(af[1][0],  af[1][1],  af[1][2],  af[1][3],  aAddr + TILE16 + ko);
            LDSM4(afl[0][0], afl[0][1], afl[0][2], afl[0][3], aAddr + LOOFF + ko);
            LDSM4(afl[1][0], afl[1][1], afl[1][2], afl[1][3], aAddr + TILE16 + LOOFF + ko);

            uint32_t bf[4][2], bfl[4][2];
            LDSM4(bf[0][0],  bf[1][0],  bf[0][1],  bf[1][1],  bAddr + ko);
            LDSM4(bf[2][0],  bf[3][0],  bf[2][1],  bf[3][1],  bAddr + TILE16 + ko);
            LDSM4(bfl[0][0], bfl[1][0], bfl[0][1], bfl[1][1], bAddr + LOOFF + ko);
            LDSM4(bfl[2][0], bfl[3][0], bfl[2][1], bfl[3][1], bAddr + TILE16 + LOOFF + ko);

            #pragma unroll
            for (int mi = 0; mi < 2; mi++)
                #pragma unroll
                for (int nj = 0; nj < 4; nj++) {
                    MMA_TF32(c[mi][nj], af[mi],  bf[nj]);    // hi*hi
                    MMA_TF32(c[mi][nj], af[mi],  bfl[nj]);   // hi*lo
                    MMA_TF32(c[mi][nj], afl[mi], bf[nj]);    // lo*hi
                }
        }

        if (kt + 1 < NKT) {
            __syncthreads();
            store_tile();
            __syncthreads();
        }
    }

    const int gid = lane >> 2;
    const int tig = lane & 3;
    #pragma unroll
    for (int mi = 0; mi < 2; mi++) {
        const int row = m0 + wm * 32 + mi * 16 + gid;
        #pragma unroll
        for (int nj = 0; nj < 4; nj++) {
            const int col = n0 + wn * 32 + nj * 8 + tig * 2;
            *(float2*)(C + (size_t)row * DD + col) =
                make_float2(c[mi][nj][0], c[mi][nj][1]);
            *(float2*)(C + (size_t)(row + 8) * DD + col) =
                make_float2(c[mi][nj][2], c[mi][nj][3]);
        }
    }
}

// ===========================================================================
// GEMM2 partial: single-pass tf32 (pre-rounded inputs, no in-loop cvt),
// double-buffered, split-K, LDSM fragments.
// ===========================================================================
template<int K, int KS>
__global__ void __launch_bounds__(128)
gemm_db_part(const float* __restrict__ A, const float* __restrict__ Bm,
             float* __restrict__ Cp)
{
    constexpr int PITCH = 36;
    constexpr int NKT   = KS / 32;

    __shared__ __align__(16) uint32_t As[2][64][PITCH];
    __shared__ __align__(16) uint32_t Bs[2][64][PITCH];

    const int tid  = threadIdx.x;
    const int lane = tid & 31;
    const int warp = tid >> 5;
    const int wm   = warp >> 1;
    const int wn   = warp & 1;

    const int m0 = blockIdx.y * 64;
    const int n0 = blockIdx.x * 64;
    const int kbase = blockIdx.z * KS;
    float* __restrict__ C = Cp + (size_t)blockIdx.z * (BB * DD);

    const int lr = tid >> 3;
    const int lc = tid & 7;

    const int q  = lane >> 3;
    const int jj = lane & 7;
    const int frow = jj + 8 * (q & 1);
    const int fcol = 4 * (q >> 1);

    const uint32_t aBase = smem_u32(&As[0][0][0]);
    const uint32_t bBase = smem_u32(&Bs[0][0][0]);
    const uint32_t aAddr = aBase + ((wm * 32 + frow) * PITCH + fcol) * 4;
    const uint32_t bAddr = bBase + ((wn * 32 + frow) * PITCH + fcol) * 4;
    constexpr uint32_t TILE16  = 16u * PITCH * 4;
    constexpr uint32_t BUFSTR  = 64u * PITCH * 4;

    float c[2][4][4];
    #pragma unroll
    for (int i = 0; i < 2; i++)
        #pragma unroll
        for (int j = 0; j < 4; j++)
            #pragma unroll
            for (int qq = 0; qq < 4; qq++) c[i][j][qq] = 0.f;

    uint4 pa[4], pb[4];

    auto load_tile = [&](int kk) {
        #pragma unroll
        for (int i = 0; i < 4; i++) {
            const int r = lr + i * 16;
            pa[i] = *(const uint4*)(A  + (size_t)(m0 + r) * K + kk + lc * 4);
            pb[i] = *(const uint4*)(Bm + (size_t)(n0 + r) * K + kk + lc * 4);
        }
    };
    auto store_tile = [&](int buf) {
        #pragma unroll
        for (int i = 0; i < 4; i++) {
            const int r = lr + i * 16;
            *(uint4*)&As[buf][r][lc * 4] = pa[i];
            *(uint4*)&Bs[buf][r][lc * 4] = pb[i];
        }
    };

    load_tile(kbase);
    store_tile(0);
    __syncthreads();

    for (int kt = 0; kt < NKT; kt++) {
        const uint32_t boff = (uint32_t)(kt & 1) * BUFSTR;
        if (kt + 1 < NKT) load_tile(kbase + (kt + 1) * 32);

        #pragma unroll
        for (int k8 = 0; k8 < 4; k8++) {
            const uint32_t ko = boff + (uint32_t)k8 * 32;

            uint32_t af[2][4];
            LDSM4(af[0][0], af[0][1], af[0][2], af[0][3], aAddr + ko);
            LDSM4(af[1][0], af[1][1], af[1][2], af[1][3], aAddr + TILE16 + ko);

            uint32_t bf[4][2];
            LDSM4(bf[0][0], bf[1][0], bf[0][1], bf[1][1], bAddr + ko);
            LDSM4(bf[2][0], bf[3][0], bf[2][1], bf[3][1], bAddr + TILE16 + ko);

            #pragma unroll
            for (int mi = 0; mi < 2; mi++)
                #pragma unroll
                for (int nj = 0; nj < 4; nj++)
                    MMA_TF32(c[mi][nj], af[mi], bf[nj]);
        }

        if (kt + 1 < NKT) store_tile((kt & 1) ^ 1);
        __syncthreads();
    }

    const int gid = lane >> 2;
    const int tig = lane & 3;
    #pragma unroll
    for (int mi = 0; mi < 2; mi++) {
        const int row = m0 + wm * 32 + mi * 16 + gid;
        #pragma unroll
        for (int nj = 0; nj < 4; nj++) {
            const int col = n0 + wn * 32 + nj * 8 + tig * 2;
            *(float2*)(C + (size_t)row * DD + col) =
                make_float2(c[mi][nj][0], c[mi][nj][1]);
            *(float2*)(C + (size_t)(row + 8) * DD + col) =
                make_float2(c[mi][nj][2], c[mi][nj][3]);
        }
    }
}

// ---------------------------------------------------------------------------
// Fused: t = tanh(sum_z p[z] + bias); tn = t/||t||; also emits tf32 copy.
// ---------------------------------------------------------------------------
__global__ void __launch_bounds__(256)
reduce_tanh_norm_kernel(const float* __restrict__ parts,
                        const float* __restrict__ bias,
                        float* __restrict__ out, float* __restrict__ outh)
{
    const int b = blockIdx.x;
    const int t = threadIdx.x;
    const int lane = t & 31, warp = t >> 5;

    float4 s  = ((const float4*)(parts + (size_t)b * DD))[t];
    #pragma unroll
    for (int z = 1; z < NSPLIT; z++) {
        float4 a = ((const float4*)(parts + (size_t)z * (BB * DD) + (size_t)b * DD))[t];
        s.x += a.x; s.y += a.y; s.z += a.z; s.w += a.w;
    }
    float4 bb = ((const float4*)bias)[t];
    float4 v;
    v.x = tanhf(s.x + bb.x);
    v.y = tanhf(s.y + bb.y);
    v.z = tanhf(s.z + bb.z);
    v.w = tanhf(s.w + bb.w);

    float ss = v.x*v.x + v.y*v.y + v.z*v.z + v.w*v.w;
    #pragma unroll
    for (int o = 16; o; o >>= 1) ss += __shfl_xor_sync(0xffffffffu, ss, o);

    __shared__ float sred[8];
    __shared__ float sinv;
    if (lane == 0) sred[warp] = ss;
    __syncthreads();
    if (t == 0) {
        float tot = 0.f;
        #pragma unroll
        for (int w = 0; w < 8; w++) tot += sred[w];
        sinv = 1.0f / fmaxf(sqrtf(tot), 1e-12f);
    }
    __syncthreads();
    const float inv = sinv;
    v.x *= inv; v.y *= inv; v.z *= inv; v.w *= inv;
    ((float4*)(out + (size_t)b * DD))[t] = v;
    ((float4*)(outh + (size_t)b * DD))[t] =
        make_float4(f2tf32f(v.x), f2tf32f(v.y), f2tf32f(v.z), f2tf32f(v.w));
}

// ---------------------------------------------------------------------------
// out = sum_z p[z] (vectorized, fixed order => deterministic)
// ---------------------------------------------------------------------------
__global__ void __launch_bounds__(256)
reduce_add_kernel(const float* __restrict__ parts, float* __restrict__ out)
{
    const int i = blockIdx.x * 256 + threadIdx.x;
    float4 s = ((const float4*)parts)[i];
    #pragma unroll
    for (int z = 1; z < NSPLIT; z++) {
        float4 a = ((const float4*)(parts + (size_t)z * (BB * DD)))[i];
        s.x += a.x; s.y += a.y; s.z += a.z; s.w += a.w;
    }
    ((float4*)out)[i] = s;
}

// ---------------------------------------------------------------------------
// sims + argmax + gather (HBM-bound; reads 1 GB once). 2-patch interleave
// for MLP; order-independent first-index tie-break.
// ---------------------------------------------------------------------------
__global__ void __launch_bounds__(256)
sims_argmax_kernel(const float* __restrict__ visual,
                   const float* __restrict__ tn,
                   float* __restrict__ vbh)
{
    const int b = blockIdx.x;
    const int lane = threadIdx.x & 31;
    const int warp = threadIdx.x >> 5;

    const float4* v4 = (const float4*)(visual + (size_t)b * PP * DD);
    const float4* t4 = (const float4*)(tn + (size_t)b * DD);

    float4 tr[8];
    #pragma unroll
    for (int k = 0; k < 8; k++) tr[k] = t4[lane + 32 * k];

    float best = -1e30f; int bidx = 1 << 30; float bss = 1.f;

    for (int pp = 0; pp < 16; pp++) {
        const int p0 = warp * 32 + pp;
        const int p1 = p0 + 16;
        const float4* r0 = v4 + (size_t)p0 * (DD / 4);
        const float4* r1 = v4 + (size_t)p1 * (DD / 4);
        float dot0 = 0.f, ss0 = 0.f, dot1 = 0.f, ss1 = 0.f;
        #pragma unroll
        for (int k = 0; k < 8; k++) {
            float4 v0 = r0[lane + 32 * k];
            float4 v1 = r1[lane + 32 * k];
            dot0 += v0.x * tr[k].x + v0.y * tr[k].y + v0.z * tr[k].z + v0.w * tr[k].w;
            ss0  += v0.x * v0.x + v0.y * v0.y + v0.z * v0.z + v0.w * v0.w;
            dot1 += v1.x * tr[k].x + v1.y * tr[k].y + v1.z * tr[k].z + v1.w * tr[k].w;
            ss1  += v1.x * v1.x + v1.y * v1.y + v1.z * v1.z + v1.w * v1.w;
        }
        #pragma unroll
        for (int o = 16; o; o >>= 1) {
            dot0 += __shfl_xor_sync(0xffffffffu, dot0, o);
            ss0  += __shfl_xor_sync(0xffffffffu, ss0,  o);
            dot1 += __shfl_xor_sync(0xffffffffu, dot1, o);
            ss1  += __shfl_xor_sync(0xffffffffu, ss1,  o);
        }
        const float sim0 = dot0 / fmaxf(sqrtf(ss0), 1e-12f);
        const float sim1 = dot1 / fmaxf(sqrtf(ss1), 1e-12f);
        if (sim0 > best || (sim0 == best && p0 < bidx)) { best = sim0; bidx = p0; bss = ss0; }
        if (sim1 > best || (sim1 == best && p1 < bidx)) { best = sim1; bidx = p1; bss = ss1; }
    }

    __shared__ float sval[8]; __shared__ int sidx[8]; __shared__ float ssum[8];
    __shared__ int s_p; __shared__ float s_inv;
    if (lane == 0) { sval[warp] = best; sidx[warp] = bidx; ssum[warp] = bss; }
    __syncthreads();
    if (threadIdx.x == 0) {
        float bv = sval[0]; int bi = sidx[0]; float bs = ssum[0];
        #pragma unroll
        for (int w = 1; w < 8; w++) {
            if (sval[w] > bv || (sval[w] == bv && sidx[w] < bi)) {
                bv = sval[w]; bi = sidx[w]; bs = ssum[w];
            }
        }
        s_p = bi;
        s_inv = 1.0f / fmaxf(sqrtf(bs), 1e-12f);
    }
    __syncthreads();

    const int p = s_p;
    const float inv = s_inv;
    const float4* row = v4 + (size_t)p * (DD / 4);
    float4* oh = (float4*)(vbh + (size_t)b * DD);
    for (int i = threadIdx.x; i < DD / 4; i += 256) {
        float4 v = row[i];
        oh[i] = make_float4(f2tf32f(v.x * inv), f2tf32f(v.y * inv),
                            f2tf32f(v.z * inv), f2tf32f(v.w * inv));
    }
}

// ---------------------------------------------------------------------------
extern "C" void kernel_launch(void* const* d_in, const int* in_sizes, int n_in,
                              void* d_out, int out_size)
{
    const float* visual = (const float*)d_in[0];   // [1024, 256, 1024]
    const float* text   = (const float*)d_in[1];   // [1024, 512]
    const float* W      = (const float*)d_in[2];   // [1024, 512]
    const float* bias   = (const float*)d_in[3];   // [1024]
    float* out = (float*)d_out;                    // [1024, 1024]

    float *p_tn, *p_tnh, *p_vbh, *p_th, *p_tl, *p_Wh, *p_Wl, *p_part;
    cudaGetSymbolAddress((void**)&p_tn,   g_tn);
    cudaGetSymbolAddress((void**)&p_tnh,  g_tnh);
    cudaGetSymbolAddress((void**)&p_vbh,  g_vbh);
    cudaGetSymbolAddress((void**)&p_th,   g_th);
    cudaGetSymbolAddress((void**)&p_tl,   g_tl);
    cudaGetSymbolAddress((void**)&p_Wh,   g_Wh);
    cudaGetSymbolAddress((void**)&p_Wl,   g_Wl);
    cudaGetSymbolAddress((void**)&p_part, g_part);

    // 0) hi/lo tf32 split of text and W (both 131072 float4)
    prep_split_kernel<<<(BB * DC / 4) / 256, 256>>>(text, W, p_th, p_tl, p_Wh, p_Wl);
    // 1) partials of text @ W^T  (split-tf32, split-K=4, pre-split inputs)
    gemm_split_part<DC, DC/NSPLIT><<<dim3(16, 16, NSPLIT), 128>>>(
        p_th, p_tl, p_Wh, p_Wl, p_part);
    // 2) tn = l2norm(tanh(sum parts + bias)); also tf32 copy for GEMM2
    reduce_tanh_norm_kernel<<<BB, 256>>>(p_part, bias, p_tn, p_tnh);
    // 3) per-b argmax over patches + gather tf32 normalized best patch
    sims_argmax_kernel<<<BB, 256>>>(visual, p_tn, p_vbh);
    // 4) partials of tn @ vb^T  (single-pass tf32, split-K=4, pre-rounded)
    gemm_db_part<DD, DD/NSPLIT><<<dim3(16, 16, NSPLIT), 128>>>(p_tnh, p_vbh, p_part);
    // 5) out = sum parts
    reduce_add_kernel<<<BB * DD / 4 / 256, 256>>>(p_part, out);
}

// round 17
// speedup vs baseline: 1.0474x; 1.0474x over previous
#include <cuda_runtime.h>
#include <math.h>
#include <stdint.h>

// Shapes (fixed for this problem)
#define BB  1024   // batch
#define PP  256    // patches
#define DD  1024   // dino dim
#define DC  512    // clip dim

#define NSPLIT 4   // split-K factor for both GEMMs

// Scratch (no allocation allowed)
__device__ float g_tn  [BB * DD];          // normalized t (fp32, argmax-critical)
__device__ float g_tnh [BB * DD];          // tf32-rounded tn (GEMM2 A)
__device__ float g_vbh [BB * DD];          // tf32-rounded vb  (GEMM2 B)
__device__ float g_th  [BB * DC];          // tf32 hi of text
__device__ float g_tl  [BB * DC];          // tf32 lo of text
__device__ float g_Wh  [DD * DC];          // tf32 hi of W
__device__ float g_Wl  [DD * DC];          // tf32 lo of W
__device__ float g_part[NSPLIT][BB * DD];  // split-K partial sums (reused)

__device__ __forceinline__ float f2tf32f(float f) {
    uint32_t u;
    asm("cvt.rna.tf32.f32 %0, %1;" : "=r"(u) : "f"(f));
    return __uint_as_float(u);
}
__device__ __forceinline__ uint32_t smem_u32(const void* p) {
    uint32_t r;
    asm("{ .reg .u64 t; cvta.to.shared.u64 t, %1; cvt.u32.u64 %0, t; }"
        : "=r"(r) : "l"(p));
    return r;
}

#define MMA_TF32(acc, a, b) \
    asm volatile( \
        "mma.sync.aligned.m16n8k8.row.col.f32.tf32.tf32.f32 " \
        "{%0,%1,%2,%3}, {%4,%5,%6,%7}, {%8,%9}, {%0,%1,%2,%3};" \
        : "+f"((acc)[0]), "+f"((acc)[1]), "+f"((acc)[2]), "+f"((acc)[3]) \
        : "r"((a)[0]), "r"((a)[1]), "r"((a)[2]), "r"((a)[3]), \
          "r"((b)[0]), "r"((b)[1]))

#define LDSM4(r0, r1, r2, r3, addr) \
    asm volatile("ldmatrix.sync.aligned.m8n8.x4.shared.b16 {%0,%1,%2,%3}, [%4];" \
        : "=r"(r0), "=r"(r1), "=r"(r2), "=r"(r3) : "r"(addr))

// ---------------------------------------------------------------------------
// Prep: hi/lo tf32 split of text and W (both 512K floats = 131072 float4).
// ---------------------------------------------------------------------------
__global__ void __launch_bounds__(256)
prep_split_kernel(const float* __restrict__ text, const float* __restrict__ W,
                  float* __restrict__ th, float* __restrict__ tl,
                  float* __restrict__ Wh, float* __restrict__ Wl)
{
    const int i = blockIdx.x * 256 + threadIdx.x;
    float4 a = ((const float4*)text)[i];
    float4 b = ((const float4*)W)[i];
    float4 ah = make_float4(f2tf32f(a.x), f2tf32f(a.y), f2tf32f(a.z), f2tf32f(a.w));
    float4 bh = make_float4(f2tf32f(b.x), f2tf32f(b.y), f2tf32f(b.z), f2tf32f(b.w));
    float4 al = make_float4(f2tf32f(a.x - ah.x), f2tf32f(a.y - ah.y),
                            f2tf32f(a.z - ah.z), f2tf32f(a.w - ah.w));
    float4 bl = make_float4(f2tf32f(b.x - bh.x), f2tf32f(b.y - bh.y),
                            f2tf32f(b.z - bh.z), f2tf32f(b.w - bh.w));
    ((float4*)th)[i] = ah; ((float4*)tl)[i] = al;
    ((float4*)Wh)[i] = bh; ((float4*)Wl)[i] = bl;
}

// ===========================================================================
// GEMM1 partial: split-tf32 (pre-split hi/lo inputs, no in-loop cvt),
// split-K over blockIdx.z. BM=BN=64, 128 threads, LDSM fragments.
// ===========================================================================
template<int K, int KS>
__global__ void __launch_bounds__(128)
gemm_split_part(const float* __restrict__ Ah, const float* __restrict__ Al,
                const float* __restrict__ Bh, const float* __restrict__ Bl,
                float* __restrict__ Cp)
{
    constexpr int PITCH = 68;            // hi at [0,32), lo at [32,64)
    constexpr int NKT   = KS / 32;

    __shared__ __align__(16) uint32_t As[64][PITCH];
    __shared__ __align__(16) uint32_t Bs[64][PITCH];

    const int tid  = threadIdx.x;
    const int lane = tid & 31;
    const int warp = tid >> 5;
    const int wm   = warp >> 1;
    const int wn   = warp & 1;

    const int m0 = blockIdx.y * 64;
    const int n0 = blockIdx.x * 64;
    const int kbase = blockIdx.z * KS;
    float* __restrict__ C = Cp + (size_t)blockIdx.z * (BB * DD);

    const int lr = tid >> 3;
    const int lc = tid & 7;

    const int q  = lane >> 3;
    const int jj = lane & 7;
    const int frow = jj + 8 * (q & 1);
    const int fcol = 4 * (q >> 1);

    const uint32_t aBase = smem_u32(&As[0][0]);
    const uint32_t bBase = smem_u32(&Bs[0][0]);
    const uint32_t aAddr = aBase + ((wm * 32 + frow) * PITCH + fcol) * 4;
    const uint32_t bAddr = bBase + ((wn * 32 + frow) * PITCH + fcol) * 4;
    constexpr uint32_t TILE16 = 16u * PITCH * 4;
    constexpr uint32_t LOOFF  = 32u * 4;

    float c[2][4][4];
    #pragma unroll
    for (int i = 0; i < 2; i++)
        #pragma unroll
        for (int j = 0; j < 4; j++)
            #pragma unroll
            for (int qq = 0; qq < 4; qq++) c[i][j][qq] = 0.f;

    uint4 pah[4], pal[4], pbh[4], pbl[4];

    auto load_tile = [&](int kk) {
        #pragma unroll
        for (int i = 0; i < 4; i++) {
            const int r = lr + i * 16;
            const size_t ao = (size_t)(m0 + r) * K + kk + lc * 4;
            const size_t bo = (size_t)(n0 + r) * K + kk + lc * 4;
            pah[i] = *(const uint4*)(Ah + ao);
            pal[i] = *(const uint4*)(Al + ao);
            pbh[i] = *(const uint4*)(Bh + bo);
            pbl[i] = *(const uint4*)(Bl + bo);
        }
    };
    auto store_tile = [&]() {
        #pragma unroll
        for (int i = 0; i < 4; i++) {
            const int r = lr + i * 16;
            *(uint4*)&As[r][lc * 4]      = pah[i];
            *(uint4*)&As[r][32 + lc * 4] = pal[i];
            *(uint4*)&Bs[r][lc * 4]      = pbh[i];
            *(uint4*)&Bs[r][32 + lc * 4] = pbl[i];
        }
    };

    load_tile(kbase);
    store_tile();
    __syncthreads();

    for (int kt = 0; kt < NKT; kt++) {
        if (kt + 1 < NKT) load_tile(kbase + (kt + 1) * 32);

        #pragma unroll
        for (int k8 = 0; k8 < 4; k8++) {
            const uint32_t ko = (uint32_t)k8 * 32;

            uint32_t af[2][4], afl[2][4];
            LDSM4(af[0][0],  af[0][1],  af[0][2],  af[0][3],  aAddr + ko);
            LDSM4(af[1][0],  af[1][1],  af[1][2],  af[1][3],  aAddr + TILE16 + ko);
            LDSM4(afl[0][0], afl[0][1], afl[0][2], afl[0][3], aAddr + LOOFF + ko);
            LDSM4(afl[1][0], afl[1][1], afl[1][2], afl[1][3], aAddr + TILE16 + LOOFF + ko);

            uint32_t bf[4][2], bfl[4][2];
            LDSM4(bf[0][0],  bf[1][0],  bf[0][1],  bf[1][1],  bAddr + ko);
            LDSM4(bf[2][0],  bf[3][0],  bf[2][1],  bf[3][1],  bAddr + TILE16 + ko);
            LDSM4(bfl[0][0], bfl[1][0], bfl[0][1], bfl[1][1], bAddr + LOOFF + ko);
            LDSM4(bfl[2][0], bfl[3][0], bfl[2][1], bfl[3][1], bAddr + TILE16 + LOOFF + ko);

            #pragma unroll
            for (int mi = 0; mi < 2; mi++)
                #pragma unroll
                for (int nj = 0; nj < 4; nj++) {
                    MMA_TF32(c[mi][nj], af[mi],  bf[nj]);    // hi*hi
                    MMA_TF32(c[mi][nj], af[mi],  bfl[nj]);   // hi*lo
                    MMA_TF32(c[mi][nj], afl[mi], bf[nj]);    // lo*hi
                }
        }

        if (kt + 1 < NKT) {
            __syncthreads();
            store_tile();
            __syncthreads();
        }
    }

    const int gid = lane >> 2;
    const int tig = lane & 3;
    #pragma unroll
    for (int mi = 0; mi < 2; mi++) {
        const int row = m0 + wm * 32 + mi * 16 + gid;
        #pragma unroll
        for (int nj = 0; nj < 4; nj++) {
            const int col = n0 + wn * 32 + nj * 8 + tig * 2;
            *(float2*)(C + (size_t)row * DD + col) =
                make_float2(c[mi][nj][0], c[mi][nj][1]);
            *(float2*)(C + (size_t)(row + 8) * DD + col) =
                make_float2(c[mi][nj][2], c[mi][nj][3]);
        }
    }
}

// ===========================================================================
// GEMM2 partial: single-pass tf32 (pre-rounded inputs, no in-loop cvt),
// double-buffered, split-K, LDSM fragments.
// ===========================================================================
template<int K, int KS>
__global__ void __launch_bounds__(128)
gemm_db_part(const float* __restrict__ A, const float* __restrict__ Bm,
             float* __restrict__ Cp)
{
    constexpr int PITCH = 36;
    constexpr int NKT   = KS / 32;

    __shared__ __align__(16) uint32_t As[2][64][PITCH];
    __shared__ __align__(16) uint32_t Bs[2][64][PITCH];

    const int tid  = threadIdx.x;
    const int lane = tid & 31;
    const int warp = tid >> 5;
    const int wm   = warp >> 1;
    const int wn   = warp & 1;

    const int m0 = blockIdx.y * 64;
    const int n0 = blockIdx.x * 64;
    const int kbase = blockIdx.z * KS;
    float* __restrict__ C = Cp + (size_t)blockIdx.z * (BB * DD);

    const int lr = tid >> 3;
    const int lc = tid & 7;

    const int q  = lane >> 3;
    const int jj = lane & 7;
    const int frow = jj + 8 * (q & 1);
    const int fcol = 4 * (q >> 1);

    const uint32_t aBase = smem_u32(&As[0][0][0]);
    const uint32_t bBase = smem_u32(&Bs[0][0][0]);
    const uint32_t aAddr = aBase + ((wm * 32 + frow) * PITCH + fcol) * 4;
    const uint32_t bAddr = bBase + ((wn * 32 + frow) * PITCH + fcol) * 4;
    constexpr uint32_t TILE16  = 16u * PITCH * 4;
    constexpr uint32_t BUFSTR  = 64u * PITCH * 4;

    float c[2][4][4];
    #pragma unroll
    for (int i = 0; i < 2; i++)
        #pragma unroll
        for (int j = 0; j < 4; j++)
            #pragma unroll
            for (int qq = 0; qq < 4; qq++) c[i][j][qq] = 0.f;

    uint4 pa[4], pb[4];

    auto load_tile = [&](int kk) {
        #pragma unroll
        for (int i = 0; i < 4; i++) {
            const int r = lr + i * 16;
            pa[i] = *(const uint4*)(A  + (size_t)(m0 + r) * K + kk + lc * 4);
            pb[i] = *(const uint4*)(Bm + (size_t)(n0 + r) * K + kk + lc * 4);
        }
    };
    auto store_tile = [&](int buf) {
        #pragma unroll
        for (int i = 0; i < 4; i++) {
            const int r = lr + i * 16;
            *(uint4*)&As[buf][r][lc * 4] = pa[i];
            *(uint4*)&Bs[buf][r][lc * 4] = pb[i];
        }
    };

    load_tile(kbase);
    store_tile(0);
    __syncthreads();

    for (int kt = 0; kt < NKT; kt++) {
        const uint32_t boff = (uint32_t)(kt & 1) * BUFSTR;
        if (kt + 1 < NKT) load_tile(kbase + (kt + 1) * 32);

        #pragma unroll
        for (int k8 = 0; k8 < 4; k8++) {
            const uint32_t ko = boff + (uint32_t)k8 * 32;

            uint32_t af[2][4];
            LDSM4(af[0][0], af[0][1], af[0][2], af[0][3], aAddr + ko);
            LDSM4(af[1][0], af[1][1], af[1][2], af[1][3], aAddr + TILE16 + ko);

            uint32_t bf[4][2];
            LDSM4(bf[0][0], bf[1][0], bf[0][1], bf[1][1], bAddr + ko);
            LDSM4(bf[2][0], bf[3][0], bf[2][1], bf[3][1], bAddr + TILE16 + ko);

            #pragma unroll
            for (int mi = 0; mi < 2; mi++)
                #pragma unroll
                for (int nj = 0; nj < 4; nj++)
                    MMA_TF32(c[mi][nj], af[mi], bf[nj]);
        }

        if (kt + 1 < NKT) store_tile((kt & 1) ^ 1);
        __syncthreads();
    }

    const int gid = lane >> 2;
    const int tig = lane & 3;
    #pragma unroll
    for (int mi = 0; mi < 2; mi++) {
        const int row = m0 + wm * 32 + mi * 16 + gid;
        #pragma unroll
        for (int nj = 0; nj < 4; nj++) {
            const int col = n0 + wn * 32 + nj * 8 + tig * 2;
            *(float2*)(C + (size_t)row * DD + col) =
                make_float2(c[mi][nj][0], c[mi][nj][1]);
            *(float2*)(C + (size_t)(row + 8) * DD + col) =
                make_float2(c[mi][nj][2], c[mi][nj][3]);
        }
    }
}

// ---------------------------------------------------------------------------
// Fused: t = tanh(sum_z p[z] + bias); tn = t/||t||; also emits tf32 copy.
// ---------------------------------------------------------------------------
__global__ void __launch_bounds__(256)
reduce_tanh_norm_kernel(const float* __restrict__ parts,
                        const float* __restrict__ bias,
                        float* __restrict__ out, float* __restrict__ outh)
{
    const int b = blockIdx.x;
    const int t = threadIdx.x;
    const int lane = t & 31, warp = t >> 5;

    float4 s  = ((const float4*)(parts + (size_t)b * DD))[t];
    #pragma unroll
    for (int z = 1; z < NSPLIT; z++) {
        float4 a = ((const float4*)(parts + (size_t)z * (BB * DD) + (size_t)b * DD))[t];
        s.x += a.x; s.y += a.y; s.z += a.z; s.w += a.w;
    }
    float4 bb = ((const float4*)bias)[t];
    float4 v;
    v.x = tanhf(s.x + bb.x);
    v.y = tanhf(s.y + bb.y);
    v.z = tanhf(s.z + bb.z);
    v.w = tanhf(s.w + bb.w);

    float ss = v.x*v.x + v.y*v.y + v.z*v.z + v.w*v.w;
    #pragma unroll
    for (int o = 16; o; o >>= 1) ss += __shfl_xor_sync(0xffffffffu, ss, o);

    __shared__ float sred[8];
    __shared__ float sinv;
    if (lane == 0) sred[warp] = ss;
    __syncthreads();
    if (t == 0) {
        float tot = 0.f;
        #pragma unroll
        for (int w = 0; w < 8; w++) tot += sred[w];
        sinv = 1.0f / fmaxf(sqrtf(tot), 1e-12f);
    }
    __syncthreads();
    const float inv = sinv;
    v.x *= inv; v.y *= inv; v.z *= inv; v.w *= inv;
    ((float4*)(out + (size_t)b * DD))[t] = v;
    ((float4*)(outh + (size_t)b * DD))[t] =
        make_float4(f2tf32f(v.x), f2tf32f(v.y), f2tf32f(v.z), f2tf32f(v.w));
}

// ---------------------------------------------------------------------------
// out = sum_z p[z] (vectorized, fixed order => deterministic)
// ---------------------------------------------------------------------------
__global__ void __launch_bounds__(256)
reduce_add_kernel(const float* __restrict__ parts, float* __restrict__ out)
{
    const int i = blockIdx.x * 256 + threadIdx.x;
    float4 s = ((const float4*)parts)[i];
    #pragma unroll
    for (int z = 1; z < NSPLIT; z++) {
        float4 a = ((const float4*)(parts + (size_t)z * (BB * DD)))[i];
        s.x += a.x; s.y += a.y; s.z += a.z; s.w += a.w;
    }
    ((float4*)out)[i] = s;
}

// ---------------------------------------------------------------------------
// sims + argmax + gather (HBM-bound; reads 1 GB once). R11 loop structure
// (single patch per iteration — measured fastest at ~6.4 TB/s).
// ---------------------------------------------------------------------------
__global__ void __launch_bounds__(256)
sims_argmax_kernel(const float* __restrict__ visual,
                   const float* __restrict__ tn,
                   float* __restrict__ vbh)
{
    const int b = blockIdx.x;
    const int lane = threadIdx.x & 31;
    const int warp = threadIdx.x >> 5;

    const float4* v4 = (const float4*)(visual + (size_t)b * PP * DD);
    const float4* t4 = (const float4*)(tn + (size_t)b * DD);

    float4 tr[8];
    #pragma unroll
    for (int k = 0; k < 8; k++) tr[k] = t4[lane + 32 * k];

    float best = -1e30f; int bidx = 0; float bss = 1.f;

    #pragma unroll 2
    for (int pp = 0; pp < 32; pp++) {
        const int p = warp * 32 + pp;
        const float4* row = v4 + (size_t)p * (DD / 4);
        float dot = 0.f, ss = 0.f;
        #pragma unroll
        for (int k = 0; k < 8; k++) {
            float4 v = row[lane + 32 * k];
            dot += v.x * tr[k].x + v.y * tr[k].y + v.z * tr[k].z + v.w * tr[k].w;
            ss  += v.x * v.x + v.y * v.y + v.z * v.z + v.w * v.w;
        }
        #pragma unroll
        for (int o = 16; o; o >>= 1) {
            dot += __shfl_xor_sync(0xffffffffu, dot, o);
            ss  += __shfl_xor_sync(0xffffffffu, ss,  o);
        }
        const float sim = dot / fmaxf(sqrtf(ss), 1e-12f);
        if (sim > best) { best = sim; bidx = p; bss = ss; }   // strict > keeps first max
    }

    __shared__ float sval[8]; __shared__ int sidx[8]; __shared__ float ssum[8];
    __shared__ int s_p; __shared__ float s_inv;
    if (lane == 0) { sval[warp] = best; sidx[warp] = bidx; ssum[warp] = bss; }
    __syncthreads();
    if (threadIdx.x == 0) {
        float bv = sval[0]; int bi = sidx[0]; float bs = ssum[0];
        #pragma unroll
        for (int w = 1; w < 8; w++) {
            if (sval[w] > bv || (sval[w] == bv && sidx[w] < bi)) {
                bv = sval[w]; bi = sidx[w]; bs = ssum[w];
            }
        }
        s_p = bi;
        s_inv = 1.0f / fmaxf(sqrtf(bs), 1e-12f);
    }
    __syncthreads();

    const int p = s_p;
    const float inv = s_inv;
    const float4* row = v4 + (size_t)p * (DD / 4);
    float4* oh = (float4*)(vbh + (size_t)b * DD);
    for (int i = threadIdx.x; i < DD / 4; i += 256) {
        float4 v = row[i];
        oh[i] = make_float4(f2tf32f(v.x * inv), f2tf32f(v.y * inv),
                            f2tf32f(v.z * inv), f2tf32f(v.w * inv));
    }
}

// ---------------------------------------------------------------------------
extern "C" void kernel_launch(void* const* d_in, const int* in_sizes, int n_in,
                              void* d_out, int out_size)
{
    const float* visual = (const float*)d_in[0];   // [1024, 256, 1024]
    const float* text   = (const float*)d_in[1];   // [1024, 512]
    const float* W      = (const float*)d_in[2];   // [1024, 512]
    const float* bias   = (const float*)d_in[3];   // [1024]
    float* out = (float*)d_out;                    // [1024, 1024]

    float *p_tn, *p_tnh, *p_vbh, *p_th, *p_tl, *p_Wh, *p_Wl, *p_part;
    cudaGetSymbolAddress((void**)&p_tn,   g_tn);
    cudaGetSymbolAddress((void**)&p_tnh,  g_tnh);
    cudaGetSymbolAddress((void**)&p_vbh,  g_vbh);
    cudaGetSymbolAddress((void**)&p_th,   g_th);
    cudaGetSymbolAddress((void**)&p_tl,   g_tl);
    cudaGetSymbolAddress((void**)&p_Wh,   g_Wh);
    cudaGetSymbolAddress((void**)&p_Wl,   g_Wl);
    cudaGetSymbolAddress((void**)&p_part, g_part);

    // 0) hi/lo tf32 split of text and W (both 131072 float4)
    prep_split_kernel<<<(BB * DC / 4) / 256, 256>>>(text, W, p_th, p_tl, p_Wh, p_Wl);
    // 1) partials of text @ W^T  (split-tf32, split-K=4, pre-split inputs)
    gemm_split_part<DC, DC/NSPLIT><<<dim3(16, 16, NSPLIT), 128>>>(
        p_th, p_tl, p_Wh, p_Wl, p_part);
    // 2) tn = l2norm(tanh(sum parts + bias)); also tf32 copy for GEMM2
    reduce_tanh_norm_kernel<<<BB, 256>>>(p_part, bias, p_tn, p_tnh);
    // 3) per-b argmax over patches + gather tf32 normalized best patch
    sims_argmax_kernel<<<BB, 256>>>(visual, p_tn, p_vbh);
    // 4) partials of tn @ vb^T  (single-pass tf32, split-K=4, pre-rounded)
    gemm_db_part<DD, DD/NSPLIT><<<dim3(16, 16, NSPLIT), 128>>>(p_tnh, p_vbh, p_part);
    // 5) out = sum parts
    reduce_add_kernel<<<BB * DD / 4 / 256, 256>>>(p_part, out);
}